// round 1
// baseline (speedup 1.0000x reference)
#include <cuda_runtime.h>
#include <math.h>
#include <stdint.h>

// TopkMoeFFN: N=131072 tokens, H=128, O=128, E=8 experts, top_k=2, fp32.
// Fused kernel: per-CTA token tile -> gating (top-2 softmax) -> per-expert
// FFN with SMEM-staged weights, packed f32x2 FMA (Blackwell PTX fma.rn.f32x2).

#define NTOK   131072
#define HDIM   128
#define ODIM   128
#define NEXP   8
#define TT     128          // tokens per CTA
#define NTHR   256

#define SX_PITCH 130        // x tile pitch (words): 520B rows -> 8B aligned, mild gating conflicts only
#define SW_PITCH 132        // weight tile pitch: 528B rows -> 16B aligned, conflict-free LDS.128
#define SO_PITCH 132        // out tile pitch: 16B aligned rows

// dynamic smem layout (floats unless noted)
#define OFF_SX    0
#define OFF_SW    (OFF_SX + TT * SX_PITCH)            // 16640
#define OFF_SOUT  (OFF_SW + HDIM * SW_PITCH)          // +16896
#define OFF_SWG   (OFF_SOUT + TT * SO_PITCH)          // +16896
#define OFF_SGATE (OFF_SWG + HDIM * NEXP)             // +1024
#define OFF_END_F (OFF_SGATE + NEXP * TT)             // +1024
#define SMEM_BYTES (OFF_END_F * 4 + NEXP * TT * 2 + NEXP * 4 + 16)

static_assert(SMEM_BYTES < 227 * 1024, "smem too big");

__device__ __forceinline__ unsigned long long fma2(unsigned long long a,
                                                   unsigned long long b,
                                                   unsigned long long c) {
    unsigned long long d;
    asm("fma.rn.f32x2 %0, %1, %2, %3;" : "=l"(d) : "l"(a), "l"(b), "l"(c));
    return d;
}

__device__ __forceinline__ unsigned long long pack2(float a, float b) {
    unsigned long long d;
    asm("mov.b64 %0, {%1, %2};" : "=l"(d)
        : "r"(__float_as_uint(a)), "r"(__float_as_uint(b)));
    return d;
}

__device__ __forceinline__ float sum2(unsigned long long v) {
    unsigned int lo, hi;
    asm("mov.b64 {%0, %1}, %2;" : "=r"(lo), "=r"(hi) : "l"(v));
    return __uint_as_float(lo) + __uint_as_float(hi);
}

extern __shared__ float smem[];

__global__ void __launch_bounds__(NTHR, 1)
moe_ffn_kernel(const float* __restrict__ x,
               const float* __restrict__ w_gate,
               const float* __restrict__ w_expert,
               const float* __restrict__ b_expert,
               float* __restrict__ out) {
    float* sx    = smem + OFF_SX;     // [TT][SX_PITCH]
    float* sw    = smem + OFF_SW;     // [HDIM][SW_PITCH]
    float* sout  = smem + OFF_SOUT;   // [TT][SO_PITCH]
    float* swg   = smem + OFF_SWG;    // [HDIM][NEXP]
    float* sgate = smem + OFF_SGATE;  // [NEXP][TT]
    unsigned short* slist = (unsigned short*)(smem + OFF_END_F);  // [NEXP][TT]
    int* scnt = (int*)(slist + NEXP * TT);                        // [NEXP]

    const int tid  = threadIdx.x;
    const int lane = tid & 31;
    const int warp = tid >> 5;
    const int tok0 = blockIdx.x * TT;

    // ---- init: counts, out tile, gate weights ----
    if (tid < NEXP) scnt[tid] = 0;
    for (int i = tid; i < TT * SO_PITCH; i += NTHR) sout[i] = 0.f;
    for (int i = tid; i < HDIM * NEXP; i += NTHR) swg[i] = w_gate[i];

    // ---- load x tile (coalesced float4) ----
    {
        const float4* xg = (const float4*)(x + (size_t)tok0 * HDIM);
        for (int i = tid; i < TT * (HDIM / 4); i += NTHR) {
            float4 v = xg[i];
            int t = i >> 5;            // 32 float4 per row
            int c = (i & 31) * 4;
            float* dst = sx + t * SX_PITCH + c;
            dst[0] = v.x; dst[1] = v.y; dst[2] = v.z; dst[3] = v.w;
        }
    }
    __syncthreads();

    // ---- gating: one thread per token (threads 0..127) ----
    if (tid < TT) {
        float logit[NEXP];
#pragma unroll
        for (int e = 0; e < NEXP; e++) logit[e] = 0.f;
        const float* xr = sx + tid * SX_PITCH;
        for (int h = 0; h < HDIM; h++) {
            float xv = xr[h];
            const float* wr = swg + h * NEXP;
#pragma unroll
            for (int e = 0; e < NEXP; e++) logit[e] = fmaf(xv, wr[e], logit[e]);
        }
        // top-2 (first index wins ties, matching lax.top_k)
        int i0 = 0; float v0 = logit[0];
#pragma unroll
        for (int e = 1; e < NEXP; e++)
            if (logit[e] > v0) { v0 = logit[e]; i0 = e; }
        int i1 = -1; float v1 = -3.4e38f;
#pragma unroll
        for (int e = 0; e < NEXP; e++)
            if (e != i0 && logit[e] > v1) { v1 = logit[e]; i1 = e; }
        // softmax over the two kept logits
        float e1 = expf(v1 - v0);
        float g0 = 1.f / (1.f + e1);
        float g1 = e1 * g0;

        int p0 = atomicAdd(&scnt[i0], 1);
        slist[i0 * TT + p0] = (unsigned short)tid;
        sgate[i0 * TT + p0] = g0;
        int p1 = atomicAdd(&scnt[i1], 1);
        slist[i1 * TT + p1] = (unsigned short)tid;
        sgate[i1 * TT + p1] = g1;
    }
    __syncthreads();

    // ---- per-expert FFN ----
    for (int e = 0; e < NEXP; e++) {
        const int cnt = scnt[e];  // uniform across block
        __syncthreads();          // previous expert's compute done before sw overwrite
        if (cnt > 0) {
            const float4* wgl = (const float4*)(w_expert + (size_t)e * HDIM * ODIM);
            for (int i = tid; i < HDIM * (ODIM / 4); i += NTHR) {
                float4 v = wgl[i];
                int h = i >> 5;
                int c = (i & 31) * 4;
                *(float4*)(sw + h * SW_PITCH + c) = v;  // 16B-aligned
            }
        }
        __syncthreads();
        if (cnt > 0) {
            const int ocol = lane * 4;
            const float* wp = sw + ocol;
            // each warp: 2 tokens per pass, 8 warps -> 16 tokens per pass
            for (int base = warp * 2; base < cnt; base += 16) {
                int ta = slist[e * TT + base];
                float ga = sgate[e * TT + base];
                int tb; float gb;
                if (base + 1 < cnt) {
                    tb = slist[e * TT + base + 1];
                    gb = sgate[e * TT + base + 1];
                } else { tb = ta; gb = 0.f; }  // padded lane: contributes exact 0

                const float* xra = sx + ta * SX_PITCH;
                const float* xrb = sx + tb * SX_PITCH;

                unsigned long long a0 = 0, a1 = 0, a2 = 0, a3 = 0;
                unsigned long long b0 = 0, b1 = 0, b2 = 0, b3 = 0;
#pragma unroll 4
                for (int h = 0; h < HDIM; h += 2) {
                    float4 wlo = *(const float4*)(wp + h * SW_PITCH);
                    float4 whi = *(const float4*)(wp + (h + 1) * SW_PITCH);
                    // pack (w[h][o], w[h+1][o]) so x pairs load natively as 8B
                    unsigned long long p0 = pack2(wlo.x, whi.x);
                    unsigned long long p1 = pack2(wlo.y, whi.y);
                    unsigned long long p2 = pack2(wlo.z, whi.z);
                    unsigned long long p3 = pack2(wlo.w, whi.w);
                    unsigned long long xa = *(const unsigned long long*)(xra + h);
                    unsigned long long xb = *(const unsigned long long*)(xrb + h);
                    a0 = fma2(xa, p0, a0); a1 = fma2(xa, p1, a1);
                    a2 = fma2(xa, p2, a2); a3 = fma2(xa, p3, a3);
                    b0 = fma2(xb, p0, b0); b1 = fma2(xb, p1, b1);
                    b2 = fma2(xb, p2, b2); b3 = fma2(xb, p3, b3);
                }
                const float* bb = b_expert + e * ODIM + ocol;
                float bi0 = bb[0], bi1 = bb[1], bi2 = bb[2], bi3 = bb[3];

                float* soa = sout + ta * SO_PITCH + ocol;
                float4 ca = *(float4*)soa;
                ca.x += ga * (sum2(a0) + bi0);
                ca.y += ga * (sum2(a1) + bi1);
                ca.z += ga * (sum2(a2) + bi2);
                ca.w += ga * (sum2(a3) + bi3);
                *(float4*)soa = ca;

                float* sob = sout + tb * SO_PITCH + ocol;
                float4 cb = *(float4*)sob;
                cb.x += gb * (sum2(b0) + bi0);
                cb.y += gb * (sum2(b1) + bi1);
                cb.z += gb * (sum2(b2) + bi2);
                cb.w += gb * (sum2(b3) + bi3);
                *(float4*)sob = cb;
            }
        }
    }
    __syncthreads();

    // ---- write out tile (coalesced float4) ----
    for (int i = tid; i < TT * (ODIM / 4); i += NTHR) {
        int t = i >> 5;
        int c = (i & 31) * 4;
        float4 v = *(const float4*)(sout + t * SO_PITCH + c);
        *(float4*)(out + (size_t)(tok0 + t) * ODIM + c) = v;
    }
}

extern "C" void kernel_launch(void* const* d_in, const int* in_sizes, int n_in,
                              void* d_out, int out_size) {
    const float* x  = (const float*)d_in[0];
    const float* wg = (const float*)d_in[1];
    // d_in[2] = w_noise (inactive in eval mode)
    const float* we = (const float*)d_in[3];
    const float* be = (const float*)d_in[4];
    float* out = (float*)d_out;

    cudaFuncSetAttribute(moe_ffn_kernel,
                         cudaFuncAttributeMaxDynamicSharedMemorySize, SMEM_BYTES);
    moe_ffn_kernel<<<NTOK / TT, NTHR, SMEM_BYTES>>>(x, wg, we, be, out);
}

// round 3
// speedup vs baseline: 1.9312x; 1.9312x over previous
#include <cuda_runtime.h>
#include <cuda_bf16.h>
#include <math.h>
#include <stdint.h>

// TopkMoeFFN: N=131072, H=128, O=128, E=8, top2, fp32.
// Tensor-core path via mma.sync (m16n8k16 bf16, split precision hi/lo),
// expert-bucketed sparse tiles, gate folded into A operand.

#define NTOK 131072
#define HDIM 128
#define ODIM 128
#define NEXP 8
#define TT   128
#define NTHR 256
#define SX_PITCH 132     // fp32 words
#define SO_PITCH 132
#define WPITCH_B 272     // staged W row pitch in bytes (136 bf16)

// smem byte offsets
#define SX_B    0                      // 67584
#define SOUT_B  67584                  // 67584
#define SWHI_B  135168                 // 34816
#define SWLO_B  169984                 // 34816
#define SWG_B   204800                 // 4096
#define SB_B    208896                 // 4096
#define SGATE_B 212992                 // 4096
#define SLIST_B 217088                 // 2048 (ushort)
#define SE0_B   219136                 // 512
#define SE1_B   219648
#define SG0_B   220160
#define SG1_B   220672
#define SCNT_B  221184                 // 32
#define SMEM_BYTES 221216

static_assert(SMEM_BYTES <= 232448, "smem too big");

__device__ __forceinline__ uint32_t smem_u32(const void* p) {
    uint32_t a;
    asm("{ .reg .u64 t; cvta.to.shared.u64 t, %1; cvt.u32.u64 %0, t; }"
        : "=r"(a) : "l"(p));
    return a;
}

__device__ __forceinline__ uint32_t cvt_bf16x2(float hi, float lo) {
    uint32_t d;
    asm("cvt.rn.bf16x2.f32 %0, %1, %2;" : "=r"(d) : "f"(hi), "f"(lo));
    return d;
}

// split (f0,f1) fp32 pair -> hi bf16x2 + lo bf16x2 (residual)
__device__ __forceinline__ void split2(float f0, float f1,
                                       uint32_t& hi, uint32_t& lo) {
    hi = cvt_bf16x2(f1, f0);
    float h0 = __uint_as_float(hi << 16);
    float h1 = __uint_as_float(hi & 0xffff0000u);
    lo = cvt_bf16x2(f1 - h1, f0 - h0);
}

__device__ __forceinline__ void ldsm_x2t(uint32_t& r0, uint32_t& r1, uint32_t a) {
    asm volatile("ldmatrix.sync.aligned.m8n8.x2.trans.shared.b16 {%0,%1}, [%2];"
                 : "=r"(r0), "=r"(r1) : "r"(a));
}

__device__ __forceinline__ void mma16816(float& c0, float& c1, float& c2, float& c3,
                                         uint32_t a0, uint32_t a1, uint32_t a2,
                                         uint32_t a3, uint32_t b0, uint32_t b1) {
    asm volatile(
        "mma.sync.aligned.m16n8k16.row.col.f32.bf16.bf16.f32 "
        "{%0,%1,%2,%3}, {%4,%5,%6,%7}, {%8,%9}, {%0,%1,%2,%3};"
        : "+f"(c0), "+f"(c1), "+f"(c2), "+f"(c3)
        : "r"(a0), "r"(a1), "r"(a2), "r"(a3), "r"(b0), "r"(b1));
}

extern __shared__ char smem_raw[];

__global__ void __launch_bounds__(NTHR, 1)
moe_ffn_mma_kernel(const float* __restrict__ x,
                   const float* __restrict__ w_gate,
                   const float* __restrict__ w_expert,
                   const float* __restrict__ b_expert,
                   float* __restrict__ out) {
    float* sx    = (float*)(smem_raw + SX_B);
    float* sout  = (float*)(smem_raw + SOUT_B);
    float* swg   = (float*)(smem_raw + SWG_B);
    float* sb    = (float*)(smem_raw + SB_B);
    float* sgate = (float*)(smem_raw + SGATE_B);
    unsigned short* slist = (unsigned short*)(smem_raw + SLIST_B);
    int*   se0  = (int*)(smem_raw + SE0_B);
    int*   se1  = (int*)(smem_raw + SE1_B);
    float* sg0  = (float*)(smem_raw + SG0_B);
    float* sg1  = (float*)(smem_raw + SG1_B);
    int*   scnt = (int*)(smem_raw + SCNT_B);

    const int tid  = threadIdx.x;
    const int lane = tid & 31;
    const int warp = tid >> 5;
    const int tok0 = blockIdx.x * TT;
    const uint32_t smem_u = smem_u32(smem_raw);

    // ---- init ----
    if (tid < NEXP) scnt[tid] = 0;
    for (int i = tid; i < TT * SO_PITCH; i += NTHR) sout[i] = 0.f;
    for (int i = tid; i < HDIM * NEXP; i += NTHR) swg[i] = w_gate[i];
    for (int i = tid; i < NEXP * ODIM; i += NTHR) sb[i] = b_expert[i];

    // ---- x tile load (coalesced float4) ----
    {
        const float4* xg = (const float4*)(x + (size_t)tok0 * HDIM);
        for (int i = tid; i < TT * (HDIM / 4); i += NTHR) {
            float4 v = xg[i];
            int t = i >> 5;
            int c = (i & 31) * 4;
            *(float4*)(sx + t * SX_PITCH + c) = v;
        }
    }
    __syncthreads();

    // ---- gating: one thread per token ----
    if (tid < TT) {
        float logit[NEXP];
#pragma unroll
        for (int e = 0; e < NEXP; e++) logit[e] = 0.f;
        const float* xr = sx + tid * SX_PITCH;
        for (int h = 0; h < HDIM; h++) {
            float xv = xr[h];
            const float* wr = swg + h * NEXP;
#pragma unroll
            for (int e = 0; e < NEXP; e++) logit[e] = fmaf(xv, wr[e], logit[e]);
        }
        int i0 = 0; float v0 = logit[0];
#pragma unroll
        for (int e = 1; e < NEXP; e++)
            if (logit[e] > v0) { v0 = logit[e]; i0 = e; }
        int i1 = -1; float v1 = -3.4e38f;
#pragma unroll
        for (int e = 0; e < NEXP; e++)
            if (e != i0 && logit[e] > v1) { v1 = logit[e]; i1 = e; }
        float e1 = expf(v1 - v0);
        float g0 = 1.f / (1.f + e1);
        float g1 = e1 * g0;
        int p0 = atomicAdd(&scnt[i0], 1);
        slist[i0 * TT + p0] = (unsigned short)tid;
        sgate[i0 * TT + p0] = g0;
        int p1 = atomicAdd(&scnt[i1], 1);
        slist[i1 * TT + p1] = (unsigned short)tid;
        sgate[i1 * TT + p1] = g1;
        se0[tid] = i0; se1[tid] = i1;
        sg0[tid] = g0; sg1[tid] = g1;
    }

    const int qr = lane >> 2;          // 0..7
    const int qk = (lane & 3) * 2;     // 0,2,4,6
    // ldmatrix row address base: row (lane&15), col offset set per tile
    const uint32_t ldsm_row = (uint32_t)(lane & 15) * WPITCH_B;

    // ---- per-expert phases ----
    for (int e = 0; e < NEXP; e++) {
        __syncthreads();  // sgate/slist ready (e==0); prev MMA reads done (e>0)

        // stage W_e -> bf16 hi/lo, layout [h][o] pitch 136 bf16
        {
            const float4* wgl = (const float4*)(w_expert + (size_t)e * HDIM * ODIM);
            for (int i = tid; i < HDIM * (ODIM / 4); i += NTHR) {
                float4 v = wgl[i];
                int h = i >> 5;
                int o4 = (i & 31) * 4;
                uint32_t h0, l0, h1, l1;
                split2(v.x, v.y, h0, l0);
                split2(v.z, v.w, h1, l1);
                uint32_t off = (uint32_t)h * WPITCH_B + (uint32_t)o4 * 2;
                *(uint2*)(smem_raw + SWHI_B + off) = make_uint2(h0, h1);
                *(uint2*)(smem_raw + SWLO_B + off) = make_uint2(l0, l1);
            }
        }
        __syncthreads();

        const int cnt = scnt[e];
        if (cnt == 0) continue;
        const int mtiles = (cnt + 15) >> 4;

        for (int wi = warp; wi < mtiles * 2; wi += 8) {
            const int mt = wi >> 1;
            const int nh = wi & 1;       // which 64-output half

            // per-lane rows/tokens/gates for this m-tile
            int r0 = mt * 16 + qr, r1 = r0 + 8;
            int sl0 = r0 < cnt ? r0 : cnt - 1;
            int sl1 = r1 < cnt ? r1 : cnt - 1;
            int tk0 = slist[e * TT + sl0];
            int tk1 = slist[e * TT + sl1];
            float s0 = (r0 < cnt) ? sgate[e * TT + sl0] : 0.f;
            float s1 = (r1 < cnt) ? sgate[e * TT + sl1] : 0.f;

            const uint32_t lds_hi = smem_u + SWHI_B + ldsm_row
                                  + (uint32_t)nh * 128u;

            float acc[8][4];
#pragma unroll
            for (int nt = 0; nt < 8; nt++)
#pragma unroll
                for (int j = 0; j < 4; j++) acc[nt][j] = 0.f;

#pragma unroll
            for (int kb = 0; kb < 8; kb++) {
                const int k0 = kb * 16;
                // build A hi/lo fragments from fp32 sx, gate-scaled
                const float* p0 = sx + tk0 * SX_PITCH + k0 + qk;
                const float* p1 = sx + tk1 * SX_PITCH + k0 + qk;
                float2 x00 = *(const float2*)(p0);
                float2 x01 = *(const float2*)(p0 + 8);
                float2 x10 = *(const float2*)(p1);
                float2 x11 = *(const float2*)(p1 + 8);
                uint32_t ah0, al0, ah1, al1, ah2, al2, ah3, al3;
                split2(s0 * x00.x, s0 * x00.y, ah0, al0);
                split2(s1 * x10.x, s1 * x10.y, ah1, al1);
                split2(s0 * x01.x, s0 * x01.y, ah2, al2);
                split2(s1 * x11.x, s1 * x11.y, ah3, al3);

                const uint32_t kbase = lds_hi + (uint32_t)k0 * WPITCH_B;
#pragma unroll
                for (int nt = 0; nt < 8; nt++) {
                    uint32_t bh0, bh1, bl0, bl1;
                    uint32_t a_hi = kbase + (uint32_t)nt * 16u;
                    ldsm_x2t(bh0, bh1, a_hi);
                    ldsm_x2t(bl0, bl1, a_hi + (SWLO_B - SWHI_B));
                    mma16816(acc[nt][0], acc[nt][1], acc[nt][2], acc[nt][3],
                             ah0, ah1, ah2, ah3, bh0, bh1);
                    mma16816(acc[nt][0], acc[nt][1], acc[nt][2], acc[nt][3],
                             ah0, ah1, ah2, ah3, bl0, bl1);
                    mma16816(acc[nt][0], acc[nt][1], acc[nt][2], acc[nt][3],
                             al0, al1, al2, al3, bh0, bh1);
                }
            }

            // write back (RMW into sout; rows unique within expert phase)
#pragma unroll
            for (int nt = 0; nt < 8; nt++) {
                int col = nh * 64 + nt * 8 + qk;
                if (r0 < cnt) {
                    float2* p = (float2*)(sout + tk0 * SO_PITCH + col);
                    float2 v = *p;
                    v.x += acc[nt][0]; v.y += acc[nt][1];
                    *p = v;
                }
                if (r1 < cnt) {
                    float2* p = (float2*)(sout + tk1 * SO_PITCH + col);
                    float2 v = *p;
                    v.x += acc[nt][2]; v.y += acc[nt][3];
                    *p = v;
                }
            }
        }
    }
    __syncthreads();

    // ---- epilogue: add gated bias, coalesced store ----
    for (int i = tid; i < TT * (ODIM / 4); i += NTHR) {
        int t = i >> 5;
        int c = (i & 31) * 4;
        float g0 = sg0[t], g1 = sg1[t];
        const float* b0 = sb + se0[t] * ODIM + c;
        const float* b1 = sb + se1[t] * ODIM + c;
        float4 v = *(const float4*)(sout + t * SO_PITCH + c);
        v.x += g0 * b0[0] + g1 * b1[0];
        v.y += g0 * b0[1] + g1 * b1[1];
        v.z += g0 * b0[2] + g1 * b1[2];
        v.w += g0 * b0[3] + g1 * b1[3];
        *(float4*)(out + (size_t)(tok0 + t) * ODIM + c) = v;
    }
}

extern "C" void kernel_launch(void* const* d_in, const int* in_sizes, int n_in,
                              void* d_out, int out_size) {
    const float* x  = (const float*)d_in[0];
    const float* wg = (const float*)d_in[1];
    // d_in[2] = w_noise (inactive in eval mode)
    const float* we = (const float*)d_in[3];
    const float* be = (const float*)d_in[4];
    float* out = (float*)d_out;

    cudaFuncSetAttribute(moe_ffn_mma_kernel,
                         cudaFuncAttributeMaxDynamicSharedMemorySize, SMEM_BYTES);
    moe_ffn_mma_kernel<<<NTOK / TT, NTHR, SMEM_BYTES>>>(x, wg, we, be, out);
}

// round 4
// speedup vs baseline: 2.0499x; 1.0615x over previous
#include <cuda_runtime.h>
#include <stdint.h>
#include <math.h>

// TopkMoeFFN: N=131072, H=128, O=128, E=8, top2, fp32.
// 5-launch pipeline: gate -> scan -> place -> ffn(phase0) -> ffn(phase1).
// Dense expert-sorted 128x128x128 bf16-split mma.sync GEMM tiles.

#define NTOK  131072
#define HDIM  128
#define ODIM  128
#define NEXP  8
#define NBLK  1024          // gating blocks of 128 tokens
#define GRID3 152           // persistent FFN grid
#define WPITCH 272          // bf16 tile row pitch in bytes (136 bf16)
#define MAXT  1040

// ---------------- global scratch (__device__ BSS; no allocs) ----------------
__device__ float4 g_meta[NTOK];                       // {e0|e1<<8, g0, g1, -}
__device__ unsigned short g_r0[NTOK], g_r1[NTOK];     // in-block ranks
__device__ int g_hist0[NBLK * NEXP], g_hist1[NBLK * NEXP];
__device__ int g_base0[NBLK * NEXP], g_base1[NBLK * NEXP];
__device__ unsigned int g_tok0[NTOK], g_tok1[NTOK];
__device__ float g_gate0[NTOK], g_gate1[NTOK];
__device__ int g_te[2][MAXT], g_ts[2][MAXT], g_tv[2][MAXT];
__device__ int g_nt[2];

// ---------------- helpers ----------------
__device__ __forceinline__ uint32_t smem_u32(const void* p) {
    uint32_t a;
    asm("{ .reg .u64 t; cvta.to.shared.u64 t, %1; cvt.u32.u64 %0, t; }"
        : "=r"(a) : "l"(p));
    return a;
}

__device__ __forceinline__ uint32_t cvt_bf16x2(float hi, float lo) {
    uint32_t d;
    asm("cvt.rn.bf16x2.f32 %0, %1, %2;" : "=r"(d) : "f"(hi), "f"(lo));
    return d;
}

// split fp32 pair -> hi bf16x2 + lo bf16x2 (residual)
__device__ __forceinline__ void split2(float f0, float f1,
                                       uint32_t& hi, uint32_t& lo) {
    hi = cvt_bf16x2(f1, f0);
    float h0 = __uint_as_float(hi << 16);
    float h1 = __uint_as_float(hi & 0xffff0000u);
    lo = cvt_bf16x2(f1 - h1, f0 - h0);
}

__device__ __forceinline__ void ldsm_x2t(uint32_t& r0, uint32_t& r1, uint32_t a) {
    asm volatile("ldmatrix.sync.aligned.m8n8.x2.trans.shared.b16 {%0,%1}, [%2];"
                 : "=r"(r0), "=r"(r1) : "r"(a));
}

__device__ __forceinline__ void ldsm_x4(uint32_t& r0, uint32_t& r1,
                                        uint32_t& r2, uint32_t& r3, uint32_t a) {
    asm volatile("ldmatrix.sync.aligned.m8n8.x4.shared.b16 {%0,%1,%2,%3}, [%4];"
                 : "=r"(r0), "=r"(r1), "=r"(r2), "=r"(r3) : "r"(a));
}

__device__ __forceinline__ void mma16816(float& c0, float& c1, float& c2, float& c3,
                                         uint32_t a0, uint32_t a1, uint32_t a2,
                                         uint32_t a3, uint32_t b0, uint32_t b1) {
    asm volatile(
        "mma.sync.aligned.m16n8k16.row.col.f32.bf16.bf16.f32 "
        "{%0,%1,%2,%3}, {%4,%5,%6,%7}, {%8,%9}, {%0,%1,%2,%3};"
        : "+f"(c0), "+f"(c1), "+f"(c2), "+f"(c3)
        : "r"(a0), "r"(a1), "r"(a2), "r"(a3), "r"(b0), "r"(b1));
}

// ---------------- kernel 1: gating ----------------
// dyn smem: sx 128x132 f32 | swg 128x8 f32 | se0/se1 128 int each
#define G_SX   0
#define G_SWG  (128 * 132 * 4)              // 67584
#define G_SE0  (G_SWG + HDIM * NEXP * 4)    // +4096
#define G_SE1  (G_SE0 + 512)
#define G_SH0  (G_SE1 + 512)
#define G_SH1  (G_SH0 + 32)
#define G_SMEM (G_SH1 + 32)

extern __shared__ char smraw[];

__global__ void __launch_bounds__(128)
k_gate(const float* __restrict__ x, const float* __restrict__ wg) {
    float* sx  = (float*)(smraw + G_SX);
    float* swg = (float*)(smraw + G_SWG);
    int* se0 = (int*)(smraw + G_SE0);
    int* se1 = (int*)(smraw + G_SE1);
    int* sh0 = (int*)(smraw + G_SH0);
    int* sh1 = (int*)(smraw + G_SH1);

    const int tid = threadIdx.x;
    const int blk = blockIdx.x;
    const int tok0 = blk * 128;

    if (tid < NEXP) { sh0[tid] = 0; sh1[tid] = 0; }
    for (int i = tid; i < HDIM * NEXP; i += 128) swg[i] = wg[i];
    const float4* xg = (const float4*)(x + (size_t)tok0 * HDIM);
    for (int i = tid; i < 128 * 32; i += 128) {
        float4 v = xg[i];
        int t = i >> 5, c = (i & 31) * 4;
        *(float4*)(sx + t * 132 + c) = v;
    }
    __syncthreads();

    float logit[NEXP];
#pragma unroll
    for (int e = 0; e < NEXP; e++) logit[e] = 0.f;
    const float* xr = sx + tid * 132;
    for (int h = 0; h < HDIM; h++) {
        float xv = xr[h];
        const float* wr = swg + h * NEXP;
#pragma unroll
        for (int e = 0; e < NEXP; e++) logit[e] = fmaf(xv, wr[e], logit[e]);
    }
    int i0 = 0; float v0 = logit[0];
#pragma unroll
    for (int e = 1; e < NEXP; e++)
        if (logit[e] > v0) { v0 = logit[e]; i0 = e; }
    int i1 = -1; float v1 = -3.4e38f;
#pragma unroll
    for (int e = 0; e < NEXP; e++)
        if (e != i0 && logit[e] > v1) { v1 = logit[e]; i1 = e; }
    float e1 = expf(v1 - v0);
    float g0 = 1.f / (1.f + e1);
    float g1 = e1 * g0;

    se0[tid] = i0; se1[tid] = i1;
    atomicAdd(&sh0[i0], 1);
    atomicAdd(&sh1[i1], 1);
    __syncthreads();

    // deterministic in-block rank
    int r0 = 0, r1 = 0;
    for (int t = 0; t < 128; t++) {
        int a = se0[t], b = se1[t];
        if (t < tid) { r0 += (a == i0); r1 += (b == i1); }
    }
    int token = tok0 + tid;
    g_meta[token] = make_float4(
        __uint_as_float((unsigned)i0 | ((unsigned)i1 << 8)), g0, g1, 0.f);
    g_r0[token] = (unsigned short)r0;
    g_r1[token] = (unsigned short)r1;
    if (tid < NEXP) {
        g_hist0[blk * NEXP + tid] = sh0[tid];
        g_hist1[blk * NEXP + tid] = sh1[tid];
    }
}

// ---------------- kernel 2: scan + tile map (1 CTA) ----------------
__global__ void k_scan() {
    __shared__ int s[NBLK * NEXP];     // 32 KB
    __shared__ int scnt[NEXP], soff[NEXP];
    const int tid = threadIdx.x, lane = tid & 31, w = tid >> 5;

    for (int p = 0; p < 2; p++) {
        const int* hist = p ? g_hist1 : g_hist0;
        int* base = p ? g_base1 : g_base0;
        for (int i = tid; i < NBLK * NEXP; i += 256) s[i] = hist[i];
        __syncthreads();

        // warp w scans expert w over 1024 blocks (blocked-cyclic)
        int run = 0;
        for (int j = 0; j < NBLK / 32; j++) {
            int b = j * 32 + lane;
            int v = s[b * NEXP + w];
            int incl = v;
#pragma unroll
            for (int d = 1; d < 32; d <<= 1) {
                int t = __shfl_up_sync(0xffffffffu, incl, d);
                if (lane >= d) incl += t;
            }
            int tot = __shfl_sync(0xffffffffu, incl, 31);
            s[b * NEXP + w] = run + incl - v;   // exclusive + running
            run += tot;
        }
        if (lane == 0) scnt[w] = run;
        __syncthreads();
        if (tid == 0) {
            int o = 0;
            for (int e = 0; e < NEXP; e++) { soff[e] = o; o += scnt[e]; }
        }
        __syncthreads();
        for (int i = tid; i < NBLK * NEXP; i += 256)
            base[i] = s[i] + soff[i & 7];
        if (tid == 0) {
            int n = 0;
            for (int e = 0; e < NEXP; e++) {
                int c = scnt[e], o = soff[e];
                for (int i = 0; i < c; i += 128) {
                    g_te[p][n] = e;
                    g_ts[p][n] = o + i;
                    g_tv[p][n] = min(128, c - i);
                    n++;
                }
            }
            g_nt[p] = n;
        }
        __syncthreads();
    }
}

// ---------------- kernel 3: scatter into per-expert lists ----------------
__global__ void __launch_bounds__(128) k_place() {
    const int blk = blockIdx.x;
    const int token = blk * 128 + threadIdx.x;
    float4 m = g_meta[token];
    unsigned u = __float_as_uint(m.x);
    int e0 = u & 0xff, e1 = (u >> 8) & 0xff;
    int s0 = g_base0[blk * NEXP + e0] + g_r0[token];
    int s1 = g_base1[blk * NEXP + e1] + g_r1[token];
    g_tok0[s0] = (unsigned)token; g_gate0[s0] = m.y;
    g_tok1[s1] = (unsigned)token; g_gate1[s1] = m.z;
}

// ---------------- kernel 4: persistent dense FFN GEMM ----------------
// dyn smem: WHI 0 | WLO 34816 | AHI 69632 | ALO 104448 | BIAS 139264 |
//           TOK 143360 (128 int) | META 143872 (128 float4)
#define F_WHI  0
#define F_WLO  34816
#define F_AHI  69632
#define F_ALO  104448
#define F_BIAS 139264
#define F_TOK  143360
#define F_META 143872
#define F_SMEM 145920

__global__ void __launch_bounds__(256, 1)
k_ffn(const float* __restrict__ x, const float* __restrict__ we,
      const float* __restrict__ be, float* __restrict__ out, int p) {
    const int tid = threadIdx.x, lane = tid & 31, w = tid >> 5;
    float* sbias = (float*)(smraw + F_BIAS);
    int* stok = (int*)(smraw + F_TOK);
    float4* smeta = (float4*)(smraw + F_META);
    const uint32_t su = smem_u32(smraw);

    const unsigned* tokl = p ? g_tok1 : g_tok0;
    const float* gatel   = p ? g_gate1 : g_gate0;

    const int ntiles = g_nt[p];
    const int t0 = (int)((long long)blockIdx.x * ntiles / GRID3);
    const int t1 = (int)((long long)(blockIdx.x + 1) * ntiles / GRID3);
    if (t0 >= t1) return;

    for (int i = tid; i < NEXP * ODIM; i += 256) sbias[i] = be[i];

    int cur_e = -1;
    for (int t = t0; t < t1; t++) {
        const int e = g_te[p][t];
        const int s0 = g_ts[p][t];
        const int valid = g_tv[p][t];

        __syncthreads();   // prior GEMM reads of A/W + epilogue reads done

        if (e != cur_e) {  // stage W_e (hi/lo bf16, [h][o], pitch 272B)
            const float4* wgl = (const float4*)(we + (size_t)e * HDIM * ODIM);
            for (int i = tid; i < HDIM * 32; i += 256) {
                float4 v = wgl[i];
                int h = i >> 5, o4 = (i & 31);
                uint32_t h0, l0, h1, l1;
                split2(v.x, v.y, h0, l0);
                split2(v.z, v.w, h1, l1);
                uint32_t off = (uint32_t)h * WPITCH + (uint32_t)o4 * 8;
                *(uint2*)(smraw + F_WHI + off) = make_uint2(h0, h1);
                *(uint2*)(smraw + F_WLO + off) = make_uint2(l0, l1);
            }
            cur_e = e;
        }

        // gather A: 128 rows x 2 halves, gate-scaled, bf16 split
        {
            int row = tid >> 1, half = tid & 1;
            unsigned token = 0; float gv = 0.f;
            if (row < valid) { token = tokl[s0 + row]; gv = gatel[s0 + row]; }
            if (half == 0) {
                stok[row] = (int)token;
                if (p == 0) smeta[row] = g_meta[token];
            }
            const float4* xr = (const float4*)(x + (size_t)token * HDIM + half * 64);
            uint32_t abase = (uint32_t)row * WPITCH + (uint32_t)half * 128;
#pragma unroll
            for (int i = 0; i < 16; i++) {
                float4 v = xr[i];
                uint32_t h0, l0, h1, l1;
                split2(gv * v.x, gv * v.y, h0, l0);
                split2(gv * v.z, gv * v.w, h1, l1);
                *(uint2*)(smraw + F_AHI + abase + i * 8) = make_uint2(h0, h1);
                *(uint2*)(smraw + F_ALO + abase + i * 8) = make_uint2(l0, l1);
            }
        }
        __syncthreads();

        // GEMM: warp w -> rows [w*16, w*16+16), all 128 cols
        float acc[16][4];
#pragma unroll
        for (int nt = 0; nt < 16; nt++) {
            acc[nt][0] = 0.f; acc[nt][1] = 0.f;
            acc[nt][2] = 0.f; acc[nt][3] = 0.f;
        }
        const int grp = lane >> 3;
        const int ar = (lane & 7) + ((grp & 1) ? 8 : 0);
        const int ac = (grp >> 1) * 8;
        const uint32_t a_base = su + F_AHI
                              + (uint32_t)(w * 16 + ar) * WPITCH
                              + (uint32_t)ac * 2;
        const uint32_t b_base = su + F_WHI + (uint32_t)(lane & 15) * WPITCH;

#pragma unroll
        for (int kb = 0; kb < 8; kb++) {
            uint32_t aa = a_base + (uint32_t)kb * 32;
            uint32_t ah0, ah1, ah2, ah3, al0, al1, al2, al3;
            ldsm_x4(ah0, ah1, ah2, ah3, aa);
            ldsm_x4(al0, al1, al2, al3, aa + (F_ALO - F_AHI));
            uint32_t bb = b_base + (uint32_t)kb * 16 * WPITCH;
#pragma unroll
            for (int nt = 0; nt < 16; nt++) {
                uint32_t bh0, bh1, bl0, bl1;
                ldsm_x2t(bh0, bh1, bb + nt * 16);
                ldsm_x2t(bl0, bl1, bb + nt * 16 + (F_WLO - F_WHI));
                mma16816(acc[nt][0], acc[nt][1], acc[nt][2], acc[nt][3],
                         ah0, ah1, ah2, ah3, bh0, bh1);
                mma16816(acc[nt][0], acc[nt][1], acc[nt][2], acc[nt][3],
                         ah0, ah1, ah2, ah3, bl0, bl1);
                mma16816(acc[nt][0], acc[nt][1], acc[nt][2], acc[nt][3],
                         al0, al1, al2, al3, bh0, bh1);
            }
        }

        // epilogue: direct global writes (phase0: init+bias; phase1: RMW add)
        const int qr = lane >> 2, qk = (lane & 3) * 2;
#pragma unroll
        for (int hrow = 0; hrow < 2; hrow++) {
            int r = w * 16 + qr + hrow * 8;
            if (r >= valid) continue;
            int tk = stok[r];
            float* op = out + (size_t)tk * ODIM;
            const int ci = hrow * 2;   // acc pair index (0,1) or (2,3)
            if (p == 0) {
                float4 m = smeta[r];
                unsigned u = __float_as_uint(m.x);
                const float* b0p = sbias + (u & 0xff) * ODIM;
                const float* b1p = sbias + ((u >> 8) & 0xff) * ODIM;
                float g0 = m.y, g1 = m.z;
#pragma unroll
                for (int nt = 0; nt < 16; nt++) {
                    int col = nt * 8 + qk;
                    float2 v;
                    v.x = acc[nt][ci]     + g0 * b0p[col]     + g1 * b1p[col];
                    v.y = acc[nt][ci + 1] + g0 * b0p[col + 1] + g1 * b1p[col + 1];
                    *(float2*)(op + col) = v;
                }
            } else {
#pragma unroll
                for (int nt = 0; nt < 16; nt++) {
                    int col = nt * 8 + qk;
                    float2 o = *(float2*)(op + col);
                    o.x += acc[nt][ci];
                    o.y += acc[nt][ci + 1];
                    *(float2*)(op + col) = o;
                }
            }
        }
    }
}

// ---------------- launch ----------------
extern "C" void kernel_launch(void* const* d_in, const int* in_sizes, int n_in,
                              void* d_out, int out_size) {
    const float* x  = (const float*)d_in[0];
    const float* wg = (const float*)d_in[1];
    // d_in[2] = w_noise (inactive in eval mode)
    const float* we = (const float*)d_in[3];
    const float* be = (const float*)d_in[4];
    float* out = (float*)d_out;

    static int configured = 0;
    if (!configured) {
        cudaFuncSetAttribute(k_gate, cudaFuncAttributeMaxDynamicSharedMemorySize,
                             G_SMEM);
        cudaFuncSetAttribute(k_ffn, cudaFuncAttributeMaxDynamicSharedMemorySize,
                             F_SMEM);
        configured = 1;
    }

    k_gate<<<NBLK, 128, G_SMEM>>>(x, wg);
    k_scan<<<1, 256>>>();
    k_place<<<NBLK, 128>>>();
    k_ffn<<<GRID3, 256, F_SMEM>>>(x, we, be, out, 0);
    k_ffn<<<GRID3, 256, F_SMEM>>>(x, we, be, out, 1);
}

// round 5
// speedup vs baseline: 2.4545x; 1.1974x over previous
#include <cuda_runtime.h>
#include <stdint.h>
#include <math.h>

// TopkMoeFFN: N=131072, H=128, O=128, E=8, top2, fp32.
// gate (ballot ranks) -> scan (parallel tilemap) -> place -> ffn x2 phases.
// Dense expert-sorted 128x128x128 bf16-split mma.sync GEMM tiles,
// 512-thread FFN CTAs, 32x32 warp tiles, dual accumulation chains.

#define NTOK  131072
#define HDIM  128
#define ODIM  128
#define NEXP  8
#define NBLK  1024
#define GRID3 152
#define WPITCH 272          // bf16 tile row pitch bytes (136 bf16)
#define MAXT  1040

// ---------------- global scratch ----------------
__device__ float4 g_meta[NTOK];                       // {e0|e1<<8, g0, g1, -}
__device__ unsigned short g_r0[NTOK], g_r1[NTOK];
__device__ int g_hist0[NBLK * NEXP], g_hist1[NBLK * NEXP];
__device__ int g_base0[NBLK * NEXP], g_base1[NBLK * NEXP];
__device__ unsigned int g_tok0[NTOK], g_tok1[NTOK];
__device__ float g_gate0[NTOK], g_gate1[NTOK];
__device__ int g_te[2][MAXT], g_ts[2][MAXT], g_tv[2][MAXT];
__device__ int g_nt[2];

// ---------------- helpers ----------------
__device__ __forceinline__ uint32_t smem_u32(const void* p) {
    uint32_t a;
    asm("{ .reg .u64 t; cvta.to.shared.u64 t, %1; cvt.u32.u64 %0, t; }"
        : "=r"(a) : "l"(p));
    return a;
}

__device__ __forceinline__ uint32_t cvt_bf16x2(float hi, float lo) {
    uint32_t d;
    asm("cvt.rn.bf16x2.f32 %0, %1, %2;" : "=r"(d) : "f"(hi), "f"(lo));
    return d;
}

__device__ __forceinline__ void split2(float f0, float f1,
                                       uint32_t& hi, uint32_t& lo) {
    hi = cvt_bf16x2(f1, f0);
    float h0 = __uint_as_float(hi << 16);
    float h1 = __uint_as_float(hi & 0xffff0000u);
    lo = cvt_bf16x2(f1 - h1, f0 - h0);
}

__device__ __forceinline__ void ldsm_x2t(uint32_t& r0, uint32_t& r1, uint32_t a) {
    asm volatile("ldmatrix.sync.aligned.m8n8.x2.trans.shared.b16 {%0,%1}, [%2];"
                 : "=r"(r0), "=r"(r1) : "r"(a));
}

__device__ __forceinline__ void ldsm_x4(uint32_t& r0, uint32_t& r1,
                                        uint32_t& r2, uint32_t& r3, uint32_t a) {
    asm volatile("ldmatrix.sync.aligned.m8n8.x4.shared.b16 {%0,%1,%2,%3}, [%4];"
                 : "=r"(r0), "=r"(r1), "=r"(r2), "=r"(r3) : "r"(a));
}

__device__ __forceinline__ void mma16816(float* c,
                                         uint32_t a0, uint32_t a1, uint32_t a2,
                                         uint32_t a3, uint32_t b0, uint32_t b1) {
    asm volatile(
        "mma.sync.aligned.m16n8k16.row.col.f32.bf16.bf16.f32 "
        "{%0,%1,%2,%3}, {%4,%5,%6,%7}, {%8,%9}, {%0,%1,%2,%3};"
        : "+f"(c[0]), "+f"(c[1]), "+f"(c[2]), "+f"(c[3])
        : "r"(a0), "r"(a1), "r"(a2), "r"(a3), "r"(b0), "r"(b1));
}

// ---------------- kernel 1: gating (ballot-based ranks) ----------------
#define G_SX   0
#define G_SWG  (128 * 132 * 4)
#define G_SMEM (G_SWG + HDIM * NEXP * 4)

extern __shared__ char smraw[];

__global__ void __launch_bounds__(128)
k_gate(const float* __restrict__ x, const float* __restrict__ wg) {
    float* sx  = (float*)(smraw + G_SX);
    float* swg = (float*)(smraw + G_SWG);
    __shared__ int wh0[4][8], wh1[4][8];

    const int tid = threadIdx.x, lane = tid & 31, w = tid >> 5;
    const int blk = blockIdx.x, tok0 = blk * 128;

    for (int i = tid; i < HDIM * NEXP; i += 128) swg[i] = wg[i];
    const float4* xg = (const float4*)(x + (size_t)tok0 * HDIM);
    for (int i = tid; i < 128 * 32; i += 128) {
        float4 v = xg[i];
        int t = i >> 5, c = (i & 31) * 4;
        *(float4*)(sx + t * 132 + c) = v;
    }
    __syncthreads();

    float logit[NEXP];
#pragma unroll
    for (int e = 0; e < NEXP; e++) logit[e] = 0.f;
    const float* xr = sx + tid * 132;
    for (int h = 0; h < HDIM; h++) {
        float xv = xr[h];
        const float* wr = swg + h * NEXP;
#pragma unroll
        for (int e = 0; e < NEXP; e++) logit[e] = fmaf(xv, wr[e], logit[e]);
    }
    int i0 = 0; float v0 = logit[0];
#pragma unroll
    for (int e = 1; e < NEXP; e++)
        if (logit[e] > v0) { v0 = logit[e]; i0 = e; }
    int i1 = -1; float v1 = -3.4e38f;
#pragma unroll
    for (int e = 0; e < NEXP; e++)
        if (e != i0 && logit[e] > v1) { v1 = logit[e]; i1 = e; }
    float e1 = expf(v1 - v0);
    float g0 = 1.f / (1.f + e1);
    float g1 = e1 * g0;

    // warp-level deterministic rank (same order as old serial loop: by tid)
    unsigned ltm = (1u << lane) - 1u;
    int myr0 = 0, myr1 = 0;
#pragma unroll
    for (int e = 0; e < NEXP; e++) {
        unsigned m0 = __ballot_sync(0xffffffffu, i0 == e);
        unsigned m1 = __ballot_sync(0xffffffffu, i1 == e);
        if (i0 == e) myr0 = __popc(m0 & ltm);
        if (i1 == e) myr1 = __popc(m1 & ltm);
        if (lane == e) { wh0[w][e] = __popc(m0); wh1[w][e] = __popc(m1); }
    }
    __syncthreads();
    int r0 = myr0, r1 = myr1;
    for (int ww = 0; ww < w; ww++) { r0 += wh0[ww][i0]; r1 += wh1[ww][i1]; }

    int token = tok0 + tid;
    g_meta[token] = make_float4(
        __uint_as_float((unsigned)i0 | ((unsigned)i1 << 8)), g0, g1, 0.f);
    g_r0[token] = (unsigned short)r0;
    g_r1[token] = (unsigned short)r1;
    if (tid < NEXP) {
        g_hist0[blk * NEXP + tid] =
            wh0[0][tid] + wh0[1][tid] + wh0[2][tid] + wh0[3][tid];
        g_hist1[blk * NEXP + tid] =
            wh1[0][tid] + wh1[1][tid] + wh1[2][tid] + wh1[3][tid];
    }
}

// ---------------- kernel 2: scan + parallel tile map ----------------
__global__ void k_scan() {
    __shared__ int s[NBLK * NEXP];
    __shared__ int scnt[NEXP], soff[NEXP], ttb[NEXP + 1];
    const int tid = threadIdx.x, lane = tid & 31, w = tid >> 5;

    for (int p = 0; p < 2; p++) {
        const int* hist = p ? g_hist1 : g_hist0;
        int* base = p ? g_base1 : g_base0;
        for (int i = tid; i < NBLK * NEXP; i += 256) s[i] = hist[i];
        __syncthreads();

        int run = 0;
        for (int j = 0; j < NBLK / 32; j++) {
            int b = j * 32 + lane;
            int v = s[b * NEXP + w];
            int incl = v;
#pragma unroll
            for (int d = 1; d < 32; d <<= 1) {
                int t = __shfl_up_sync(0xffffffffu, incl, d);
                if (lane >= d) incl += t;
            }
            int tot = __shfl_sync(0xffffffffu, incl, 31);
            s[b * NEXP + w] = run + incl - v;
            run += tot;
        }
        if (lane == 0) scnt[w] = run;
        __syncthreads();
        if (tid == 0) {
            int o = 0;
            ttb[0] = 0;
            for (int e = 0; e < NEXP; e++) {
                soff[e] = o; o += scnt[e];
                ttb[e + 1] = ttb[e] + (scnt[e] + 127) / 128;
            }
            g_nt[p] = ttb[NEXP];
        }
        __syncthreads();
        for (int i = tid; i < NBLK * NEXP; i += 256)
            base[i] = s[i] + soff[i & 7];
        const int ntt = ttb[NEXP];
        for (int idx = tid; idx < ntt; idx += 256) {
            int e = 0;
            while (ttb[e + 1] <= idx) e++;
            int i = idx - ttb[e];
            g_te[p][idx] = e;
            g_ts[p][idx] = soff[e] + i * 128;
            g_tv[p][idx] = min(128, scnt[e] - i * 128);
        }
        __syncthreads();
    }
}

// ---------------- kernel 3: scatter ----------------
__global__ void __launch_bounds__(128) k_place() {
    const int blk = blockIdx.x;
    const int token = blk * 128 + threadIdx.x;
    float4 m = g_meta[token];
    unsigned u = __float_as_uint(m.x);
    int e0 = u & 0xff, e1 = (u >> 8) & 0xff;
    int s0 = g_base0[blk * NEXP + e0] + g_r0[token];
    int s1 = g_base1[blk * NEXP + e1] + g_r1[token];
    g_tok0[s0] = (unsigned)token; g_gate0[s0] = m.y;
    g_tok1[s1] = (unsigned)token; g_gate1[s1] = m.z;
}

// ---------------- kernel 4: persistent dense FFN GEMM (512 thr) ----------------
#define F_WHI  0
#define F_WLO  34816
#define F_AHI  69632
#define F_ALO  104448
#define F_BIAS 139264
#define F_TOK  143360
#define F_META 143872
#define F_SMEM 145920
#define NTHR_F 512

__global__ void __launch_bounds__(NTHR_F, 1)
k_ffn(const float* __restrict__ x, const float* __restrict__ we,
      const float* __restrict__ be, float* __restrict__ out, int p) {
    const int tid = threadIdx.x, lane = tid & 31, w = tid >> 5;
    float* sbias = (float*)(smraw + F_BIAS);
    int* stok = (int*)(smraw + F_TOK);
    float4* smeta = (float4*)(smraw + F_META);
    const uint32_t su = smem_u32(smraw);

    const unsigned* tokl = p ? g_tok1 : g_tok0;
    const float* gatel   = p ? g_gate1 : g_gate0;

    const int ntiles = g_nt[p];
    const int t0 = (int)((long long)blockIdx.x * ntiles / GRID3);
    const int t1 = (int)((long long)(blockIdx.x + 1) * ntiles / GRID3);
    if (t0 >= t1) return;

    for (int i = tid; i < NEXP * ODIM; i += NTHR_F) sbias[i] = be[i];

    // warp job: rows [mt*32, +32), cols [nq*32, +32)
    const int mt = w >> 2, nq = w & 3;
    const int grp = lane >> 3;
    const int ar = (lane & 7) + ((grp & 1) ? 8 : 0);
    const int ac = (grp >> 1) * 8;
    const uint32_t a_base0 = su + F_AHI
                           + (uint32_t)(mt * 32 + ar) * WPITCH + (uint32_t)ac * 2;
    const uint32_t a_base1 = a_base0 + 16u * WPITCH;
    const uint32_t b_base  = su + F_WHI + (uint32_t)(lane & 15) * WPITCH
                           + (uint32_t)nq * 64u;

    int cur_e = -1;
    for (int t = t0; t < t1; t++) {
        const int e = g_te[p][t];
        const int s0 = g_ts[p][t];
        const int valid = g_tv[p][t];

        __syncthreads();

        if (e != cur_e) {
            const float4* wgl = (const float4*)(we + (size_t)e * HDIM * ODIM);
            for (int i = tid; i < HDIM * 32; i += NTHR_F) {
                float4 v = wgl[i];
                int h = i >> 5, o4 = (i & 31);
                uint32_t h0, l0, h1, l1;
                split2(v.x, v.y, h0, l0);
                split2(v.z, v.w, h1, l1);
                uint32_t off = (uint32_t)h * WPITCH + (uint32_t)o4 * 8;
                *(uint2*)(smraw + F_WHI + off) = make_uint2(h0, h1);
                *(uint2*)(smraw + F_WLO + off) = make_uint2(l0, l1);
            }
            cur_e = e;
        }

        // gather A: 4 threads/row, 32 floats each
        {
            int row = tid >> 2, q = tid & 3;
            unsigned token = 0; float gv = 0.f;
            if (row < valid) { token = tokl[s0 + row]; gv = gatel[s0 + row]; }
            if (q == 0) {
                stok[row] = (int)token;
                if (p == 0) smeta[row] = g_meta[token];
            }
            const float4* xr = (const float4*)(x + (size_t)token * HDIM + q * 32);
            uint32_t abase = (uint32_t)row * WPITCH + (uint32_t)q * 64;
#pragma unroll
            for (int i = 0; i < 8; i++) {
                float4 v = xr[i];
                uint32_t h0, l0, h1, l1;
                split2(gv * v.x, gv * v.y, h0, l0);
                split2(gv * v.z, gv * v.w, h1, l1);
                *(uint2*)(smraw + F_AHI + abase + i * 8) = make_uint2(h0, h1);
                *(uint2*)(smraw + F_ALO + abase + i * 8) = make_uint2(l0, l1);
            }
        }
        __syncthreads();

        // GEMM: 2 m16 tiles x 4 n8 tiles, dual accumulation chains
        float acc[2][4][4], accB[2][4][4];
#pragma unroll
        for (int m = 0; m < 2; m++)
#pragma unroll
            for (int nt = 0; nt < 4; nt++)
#pragma unroll
                for (int j = 0; j < 4; j++) {
                    acc[m][nt][j] = 0.f; accB[m][nt][j] = 0.f;
                }

#pragma unroll
        for (int kb = 0; kb < 8; kb++) {
            uint32_t ah[2][4], al[2][4];
            uint32_t aa0 = a_base0 + (uint32_t)kb * 32;
            uint32_t aa1 = a_base1 + (uint32_t)kb * 32;
            ldsm_x4(ah[0][0], ah[0][1], ah[0][2], ah[0][3], aa0);
            ldsm_x4(al[0][0], al[0][1], al[0][2], al[0][3], aa0 + (F_ALO - F_AHI));
            ldsm_x4(ah[1][0], ah[1][1], ah[1][2], ah[1][3], aa1);
            ldsm_x4(al[1][0], al[1][1], al[1][2], al[1][3], aa1 + (F_ALO - F_AHI));
            uint32_t bb = b_base + (uint32_t)kb * 16 * WPITCH;
#pragma unroll
            for (int nt = 0; nt < 4; nt++) {
                uint32_t bh0, bh1, bl0, bl1;
                ldsm_x2t(bh0, bh1, bb + nt * 16);
                ldsm_x2t(bl0, bl1, bb + nt * 16 + (F_WLO - F_WHI));
#pragma unroll
                for (int m = 0; m < 2; m++) {
                    mma16816(acc[m][nt], ah[m][0], ah[m][1], ah[m][2], ah[m][3],
                             bh0, bh1);
                    mma16816(accB[m][nt], ah[m][0], ah[m][1], ah[m][2], ah[m][3],
                             bl0, bl1);
                    mma16816(accB[m][nt], al[m][0], al[m][1], al[m][2], al[m][3],
                             bh0, bh1);
                }
            }
        }

        // epilogue
        const int qr = lane >> 2, qk = (lane & 3) * 2;
#pragma unroll
        for (int m = 0; m < 2; m++) {
#pragma unroll
            for (int hrow = 0; hrow < 2; hrow++) {
                int r = mt * 32 + m * 16 + qr + hrow * 8;
                if (r >= valid) continue;
                int tk = stok[r];
                float* op = out + (size_t)tk * ODIM;
                const int ci = hrow * 2;
                if (p == 0) {
                    float4 mm = smeta[r];
                    unsigned u = __float_as_uint(mm.x);
                    const float* b0p = sbias + (u & 0xff) * ODIM;
                    const float* b1p = sbias + ((u >> 8) & 0xff) * ODIM;
                    float gg0 = mm.y, gg1 = mm.z;
#pragma unroll
                    for (int nt = 0; nt < 4; nt++) {
                        int col = nq * 32 + nt * 8 + qk;
                        float2 v;
                        v.x = acc[m][nt][ci] + accB[m][nt][ci]
                            + gg0 * b0p[col] + gg1 * b1p[col];
                        v.y = acc[m][nt][ci + 1] + accB[m][nt][ci + 1]
                            + gg0 * b0p[col + 1] + gg1 * b1p[col + 1];
                        *(float2*)(op + col) = v;
                    }
                } else {
#pragma unroll
                    for (int nt = 0; nt < 4; nt++) {
                        int col = nq * 32 + nt * 8 + qk;
                        float2 o = *(float2*)(op + col);
                        o.x += acc[m][nt][ci] + accB[m][nt][ci];
                        o.y += acc[m][nt][ci + 1] + accB[m][nt][ci + 1];
                        *(float2*)(op + col) = o;
                    }
                }
            }
        }
    }
}

// ---------------- launch ----------------
extern "C" void kernel_launch(void* const* d_in, const int* in_sizes, int n_in,
                              void* d_out, int out_size) {
    const float* x  = (const float*)d_in[0];
    const float* wg = (const float*)d_in[1];
    // d_in[2] = w_noise (inactive in eval mode)
    const float* we = (const float*)d_in[3];
    const float* be = (const float*)d_in[4];
    float* out = (float*)d_out;

    cudaFuncSetAttribute(k_gate, cudaFuncAttributeMaxDynamicSharedMemorySize,
                         G_SMEM);
    cudaFuncSetAttribute(k_ffn, cudaFuncAttributeMaxDynamicSharedMemorySize,
                         F_SMEM);

    k_gate<<<NBLK, 128, G_SMEM>>>(x, wg);
    k_scan<<<1, 256>>>();
    k_place<<<NBLK, 128>>>();
    k_ffn<<<GRID3, NTHR_F, F_SMEM>>>(x, we, be, out, 0);
    k_ffn<<<GRID3, NTHR_F, F_SMEM>>>(x, we, be, out, 1);
}

// round 6
// speedup vs baseline: 2.6514x; 1.0802x over previous
#include <cuda_runtime.h>
#include <stdint.h>
#include <math.h>

// TopkMoeFFN: N=131072, H=128, O=128, E=8, top2, fp32.
// gate -> scan -> place -> ffn x2. Dense expert-sorted 128x128x128
// bf16-split mma.sync tiles; cp.async-pipelined A gather.

#define NTOK  131072
#define HDIM  128
#define ODIM  128
#define NEXP  8
#define NBLK  1024
#define GRID3 152
#define WPITCH 272
#define MAXT  1040

__device__ float4 g_meta[NTOK];
__device__ unsigned short g_r0[NTOK], g_r1[NTOK];
__device__ int g_hist0[NBLK * NEXP], g_hist1[NBLK * NEXP];
__device__ int g_base0[NBLK * NEXP], g_base1[NBLK * NEXP];
__device__ unsigned int g_tok0[NTOK], g_tok1[NTOK];
__device__ float g_gate0[NTOK], g_gate1[NTOK];
__device__ int g_te[2][MAXT], g_ts[2][MAXT], g_tv[2][MAXT];
__device__ int g_nt[2];

__device__ __forceinline__ uint32_t smem_u32(const void* p) {
    uint32_t a;
    asm("{ .reg .u64 t; cvta.to.shared.u64 t, %1; cvt.u32.u64 %0, t; }"
        : "=r"(a) : "l"(p));
    return a;
}

__device__ __forceinline__ uint32_t cvt_bf16x2(float hi, float lo) {
    uint32_t d;
    asm("cvt.rn.bf16x2.f32 %0, %1, %2;" : "=r"(d) : "f"(hi), "f"(lo));
    return d;
}

__device__ __forceinline__ void split2(float f0, float f1,
                                       uint32_t& hi, uint32_t& lo) {
    hi = cvt_bf16x2(f1, f0);
    float h0 = __uint_as_float(hi << 16);
    float h1 = __uint_as_float(hi & 0xffff0000u);
    lo = cvt_bf16x2(f1 - h1, f0 - h0);
}

__device__ __forceinline__ void ldsm_x2t(uint32_t& r0, uint32_t& r1, uint32_t a) {
    asm volatile("ldmatrix.sync.aligned.m8n8.x2.trans.shared.b16 {%0,%1}, [%2];"
                 : "=r"(r0), "=r"(r1) : "r"(a));
}

__device__ __forceinline__ void ldsm_x4(uint32_t& r0, uint32_t& r1,
                                        uint32_t& r2, uint32_t& r3, uint32_t a) {
    asm volatile("ldmatrix.sync.aligned.m8n8.x4.shared.b16 {%0,%1,%2,%3}, [%4];"
                 : "=r"(r0), "=r"(r1), "=r"(r2), "=r"(r3) : "r"(a));
}

__device__ __forceinline__ void mma16816(float* c,
                                         uint32_t a0, uint32_t a1, uint32_t a2,
                                         uint32_t a3, uint32_t b0, uint32_t b1) {
    asm volatile(
        "mma.sync.aligned.m16n8k16.row.col.f32.bf16.bf16.f32 "
        "{%0,%1,%2,%3}, {%4,%5,%6,%7}, {%8,%9}, {%0,%1,%2,%3};"
        : "+f"(c[0]), "+f"(c[1]), "+f"(c[2]), "+f"(c[3])
        : "r"(a0), "r"(a1), "r"(a2), "r"(a3), "r"(b0), "r"(b1));
}

__device__ __forceinline__ void cpa16(uint32_t dst, const void* src) {
    asm volatile("cp.async.cg.shared.global [%0], [%1], 16;"
                 :: "r"(dst), "l"(src) : "memory");
}

// ---------------- kernel 1: gating ----------------
#define G_SX   0
#define G_SWG  (128 * 132 * 4)
#define G_SMEM (G_SWG + HDIM * NEXP * 4)

extern __shared__ char smraw[];

__global__ void __launch_bounds__(128)
k_gate(const float* __restrict__ x, const float* __restrict__ wg) {
    float* sx  = (float*)(smraw + G_SX);
    float* swg = (float*)(smraw + G_SWG);
    __shared__ int wh0[4][8], wh1[4][8];

    const int tid = threadIdx.x, lane = tid & 31, w = tid >> 5;
    const int blk = blockIdx.x, tok0 = blk * 128;

    for (int i = tid; i < HDIM * NEXP; i += 128) swg[i] = wg[i];
    const float4* xg = (const float4*)(x + (size_t)tok0 * HDIM);
    for (int i = tid; i < 128 * 32; i += 128) {
        float4 v = xg[i];
        int t = i >> 5, c = (i & 31) * 4;
        *(float4*)(sx + t * 132 + c) = v;
    }
    __syncthreads();

    float lg[NEXP];
#pragma unroll
    for (int e = 0; e < NEXP; e++) lg[e] = 0.f;
    const float* xr = sx + tid * 132;
#pragma unroll 4
    for (int h4 = 0; h4 < 32; h4++) {
        float4 xq = *(const float4*)(xr + h4 * 4);
        const float* wr = swg + h4 * 32;
#pragma unroll
        for (int j = 0; j < 4; j++) {
            float xv = (j == 0) ? xq.x : (j == 1) ? xq.y : (j == 2) ? xq.z : xq.w;
            float4 wa = *(const float4*)(wr + j * 8);
            float4 wb = *(const float4*)(wr + j * 8 + 4);
            lg[0] = fmaf(xv, wa.x, lg[0]); lg[1] = fmaf(xv, wa.y, lg[1]);
            lg[2] = fmaf(xv, wa.z, lg[2]); lg[3] = fmaf(xv, wa.w, lg[3]);
            lg[4] = fmaf(xv, wb.x, lg[4]); lg[5] = fmaf(xv, wb.y, lg[5]);
            lg[6] = fmaf(xv, wb.z, lg[6]); lg[7] = fmaf(xv, wb.w, lg[7]);
        }
    }
    int i0 = 0; float v0 = lg[0];
#pragma unroll
    for (int e = 1; e < NEXP; e++)
        if (lg[e] > v0) { v0 = lg[e]; i0 = e; }
    int i1 = -1; float v1 = -3.4e38f;
#pragma unroll
    for (int e = 0; e < NEXP; e++)
        if (e != i0 && lg[e] > v1) { v1 = lg[e]; i1 = e; }
    float e1 = expf(v1 - v0);
    float g0 = 1.f / (1.f + e1);
    float g1 = e1 * g0;

    unsigned ltm = (1u << lane) - 1u;
    int myr0 = 0, myr1 = 0;
#pragma unroll
    for (int e = 0; e < NEXP; e++) {
        unsigned m0 = __ballot_sync(0xffffffffu, i0 == e);
        unsigned m1 = __ballot_sync(0xffffffffu, i1 == e);
        if (i0 == e) myr0 = __popc(m0 & ltm);
        if (i1 == e) myr1 = __popc(m1 & ltm);
        if (lane == e) { wh0[w][e] = __popc(m0); wh1[w][e] = __popc(m1); }
    }
    __syncthreads();
    int r0 = myr0, r1 = myr1;
    for (int ww = 0; ww < w; ww++) { r0 += wh0[ww][i0]; r1 += wh1[ww][i1]; }

    int token = tok0 + tid;
    g_meta[token] = make_float4(
        __uint_as_float((unsigned)i0 | ((unsigned)i1 << 8)), g0, g1, 0.f);
    g_r0[token] = (unsigned short)r0;
    g_r1[token] = (unsigned short)r1;
    if (tid < NEXP) {
        g_hist0[blk * NEXP + tid] =
            wh0[0][tid] + wh0[1][tid] + wh0[2][tid] + wh0[3][tid];
        g_hist1[blk * NEXP + tid] =
            wh1[0][tid] + wh1[1][tid] + wh1[2][tid] + wh1[3][tid];
    }
}

// ---------------- kernel 2: scan ----------------
__global__ void k_scan() {
    __shared__ int s[NBLK * NEXP];
    __shared__ int scnt[NEXP], soff[NEXP], ttb[NEXP + 1];
    const int tid = threadIdx.x, lane = tid & 31, w = tid >> 5;

    for (int p = 0; p < 2; p++) {
        const int* hist = p ? g_hist1 : g_hist0;
        int* base = p ? g_base1 : g_base0;
        for (int i = tid; i < NBLK * NEXP; i += 256) s[i] = hist[i];
        __syncthreads();

        int run = 0;
        for (int j = 0; j < NBLK / 32; j++) {
            int b = j * 32 + lane;
            int v = s[b * NEXP + w];
            int incl = v;
#pragma unroll
            for (int d = 1; d < 32; d <<= 1) {
                int t = __shfl_up_sync(0xffffffffu, incl, d);
                if (lane >= d) incl += t;
            }
            int tot = __shfl_sync(0xffffffffu, incl, 31);
            s[b * NEXP + w] = run + incl - v;
            run += tot;
        }
        if (lane == 0) scnt[w] = run;
        __syncthreads();
        if (tid == 0) {
            int o = 0;
            ttb[0] = 0;
            for (int e = 0; e < NEXP; e++) {
                soff[e] = o; o += scnt[e];
                ttb[e + 1] = ttb[e] + (scnt[e] + 127) / 128;
            }
            g_nt[p] = ttb[NEXP];
        }
        __syncthreads();
        for (int i = tid; i < NBLK * NEXP; i += 256)
            base[i] = s[i] + soff[i & 7];
        const int ntt = ttb[NEXP];
        for (int idx = tid; idx < ntt; idx += 256) {
            int e = 0;
            while (ttb[e + 1] <= idx) e++;
            int i = idx - ttb[e];
            g_te[p][idx] = e;
            g_ts[p][idx] = soff[e] + i * 128;
            g_tv[p][idx] = min(128, scnt[e] - i * 128);
        }
        __syncthreads();
    }
}

// ---------------- kernel 3: scatter ----------------
__global__ void __launch_bounds__(128) k_place() {
    const int blk = blockIdx.x;
    const int token = blk * 128 + threadIdx.x;
    float4 m = g_meta[token];
    unsigned u = __float_as_uint(m.x);
    int e0 = u & 0xff, e1 = (u >> 8) & 0xff;
    int s0 = g_base0[blk * NEXP + e0] + g_r0[token];
    int s1 = g_base1[blk * NEXP + e1] + g_r1[token];
    g_tok0[s0] = (unsigned)token; g_gate0[s0] = m.y;
    g_tok1[s1] = (unsigned)token; g_gate1[s1] = m.z;
}

// ---------------- kernel 4: pipelined FFN GEMM ----------------
#define F_WHI   0
#define F_WLO   34816
#define F_AHI   69632
#define F_ALO   104448
#define F_STAGE 139264      // 64KB fp32 stage (128B per thread)
#define F_BIAS  204800
#define F_TOK   208896
#define F_META  209408
#define F_SMEM  211456
#define NTHR_F 512

__global__ void __launch_bounds__(NTHR_F, 1)
k_ffn(const float* __restrict__ x, const float* __restrict__ we,
      const float* __restrict__ be, float* __restrict__ out, int p) {
    const int tid = threadIdx.x, lane = tid & 31, w = tid >> 5;
    float* sbias = (float*)(smraw + F_BIAS);
    int* stok = (int*)(smraw + F_TOK);
    float4* smeta = (float4*)(smraw + F_META);
    const uint32_t su = smem_u32(smraw);

    const unsigned* tokl = p ? g_tok1 : g_tok0;
    const float* gatel   = p ? g_gate1 : g_gate0;

    const int ntiles = g_nt[p];
    const int t0 = (int)((long long)blockIdx.x * ntiles / GRID3);
    const int t1 = (int)((long long)(blockIdx.x + 1) * ntiles / GRID3);
    if (t0 >= t1) return;

    for (int i = tid; i < NEXP * ODIM; i += NTHR_F) sbias[i] = be[i];

    const int mt = w >> 2, nq = w & 3;
    const int grp = lane >> 3;
    const int ar = (lane & 7) + ((grp & 1) ? 8 : 0);
    const int ac = (grp >> 1) * 8;
    const uint32_t a_base0 = su + F_AHI
                           + (uint32_t)(mt * 32 + ar) * WPITCH + (uint32_t)ac * 2;
    const uint32_t a_base1 = a_base0 + 16u * WPITCH;
    const uint32_t b_base  = su + F_WHI + (uint32_t)(lane & 15) * WPITCH
                           + (uint32_t)nq * 64u;

    const int row = tid >> 2, q = tid & 3;
    const uint32_t stage_b = su + F_STAGE + (uint32_t)tid * 128u;
    char* stage_l = smraw + F_STAGE + tid * 128;

    // prologue: prefetch tile t0
    unsigned nx_token; float nx_gate;
    {
        int s0 = g_ts[p][t0], valid = g_tv[p][t0];
        nx_token = 0; nx_gate = 0.f;
        if (row < valid) { nx_token = tokl[s0 + row]; nx_gate = gatel[s0 + row]; }
        const char* src = (const char*)(x + (size_t)nx_token * HDIM + q * 32);
#pragma unroll
        for (int i = 0; i < 8; i++)
            cpa16(stage_b + (uint32_t)(((i + tid) & 7) * 16), src + i * 16);
        asm volatile("cp.async.commit_group;" ::: "memory");
    }

    int cur_e = -1;
    for (int t = t0; t < t1; t++) {
        const int e = g_te[p][t];
        const int valid = g_tv[p][t];
        const unsigned token = nx_token;
        const float gv = nx_gate;

        // early-issue next tile's token/gate loads (consumed after convert)
        if (t + 1 < t1) {
            int s0n = g_ts[p][t + 1], vn = g_tv[p][t + 1];
            nx_token = 0; nx_gate = 0.f;
            if (row < vn) { nx_token = tokl[s0n + row]; nx_gate = gatel[s0n + row]; }
        }

        __syncthreads();   // prev GEMM done: A & W writable

        if (e != cur_e) {
            const float4* wgl = (const float4*)(we + (size_t)e * HDIM * ODIM);
            for (int i = tid; i < HDIM * 32; i += NTHR_F) {
                float4 v = wgl[i];
                int h = i >> 5, o4 = (i & 31);
                uint32_t h0, l0, h1, l1;
                split2(v.x, v.y, h0, l0);
                split2(v.z, v.w, h1, l1);
                uint32_t off = (uint32_t)h * WPITCH + (uint32_t)o4 * 8;
                *(uint2*)(smraw + F_WHI + off) = make_uint2(h0, h1);
                *(uint2*)(smraw + F_WLO + off) = make_uint2(l0, l1);
            }
            cur_e = e;
        }

        // convert own staged 32 floats -> A hi/lo
        asm volatile("cp.async.wait_group 0;" ::: "memory");
        if (q == 0) {
            stok[row] = (int)token;
            if (p == 0) smeta[row] = g_meta[token];
        }
        {
            uint32_t abase = (uint32_t)row * WPITCH + (uint32_t)q * 64;
#pragma unroll
            for (int i = 0; i < 8; i++) {
                float4 v = *(const float4*)(stage_l + ((i + tid) & 7) * 16);
                uint32_t h0, l0, h1, l1;
                split2(gv * v.x, gv * v.y, h0, l0);
                split2(gv * v.z, gv * v.w, h1, l1);
                *(uint2*)(smraw + F_AHI + abase + i * 8) = make_uint2(h0, h1);
                *(uint2*)(smraw + F_ALO + abase + i * 8) = make_uint2(l0, l1);
            }
        }
        // issue prefetch for t+1 (overlaps the GEMM below)
        if (t + 1 < t1) {
            const char* src = (const char*)(x + (size_t)nx_token * HDIM + q * 32);
#pragma unroll
            for (int i = 0; i < 8; i++)
                cpa16(stage_b + (uint32_t)(((i + tid) & 7) * 16), src + i * 16);
        }
        asm volatile("cp.async.commit_group;" ::: "memory");
        __syncthreads();   // A ready

        // GEMM
        float acc[2][4][4], accB[2][4][4];
#pragma unroll
        for (int m = 0; m < 2; m++)
#pragma unroll
            for (int nt = 0; nt < 4; nt++)
#pragma unroll
                for (int j = 0; j < 4; j++) {
                    acc[m][nt][j] = 0.f; accB[m][nt][j] = 0.f;
                }

#pragma unroll
        for (int kb = 0; kb < 8; kb++) {
            uint32_t ah[2][4], al[2][4];
            uint32_t aa0 = a_base0 + (uint32_t)kb * 32;
            uint32_t aa1 = a_base1 + (uint32_t)kb * 32;
            ldsm_x4(ah[0][0], ah[0][1], ah[0][2], ah[0][3], aa0);
            ldsm_x4(al[0][0], al[0][1], al[0][2], al[0][3], aa0 + (F_ALO - F_AHI));
            ldsm_x4(ah[1][0], ah[1][1], ah[1][2], ah[1][3], aa1);
            ldsm_x4(al[1][0], al[1][1], al[1][2], al[1][3], aa1 + (F_ALO - F_AHI));
            uint32_t bb = b_base + (uint32_t)kb * 16 * WPITCH;
#pragma unroll
            for (int nt = 0; nt < 4; nt++) {
                uint32_t bh0, bh1, bl0, bl1;
                ldsm_x2t(bh0, bh1, bb + nt * 16);
                ldsm_x2t(bl0, bl1, bb + nt * 16 + (F_WLO - F_WHI));
#pragma unroll
                for (int m = 0; m < 2; m++) {
                    mma16816(acc[m][nt], ah[m][0], ah[m][1], ah[m][2], ah[m][3],
                             bh0, bh1);
                    mma16816(accB[m][nt], ah[m][0], ah[m][1], ah[m][2], ah[m][3],
                             bl0, bl1);
                    mma16816(accB[m][nt], al[m][0], al[m][1], al[m][2], al[m][3],
                             bh0, bh1);
                }
            }
        }

        // epilogue
        const int qr = lane >> 2, qk = (lane & 3) * 2;
#pragma unroll
        for (int m = 0; m < 2; m++) {
            int ra = mt * 32 + m * 16 + qr;
            int rb = ra + 8;
            bool va = ra < valid, vb = rb < valid;
            float* opa = va ? out + (size_t)stok[ra] * ODIM : 0;
            float* opb = vb ? out + (size_t)stok[rb] * ODIM : 0;
            if (p == 0) {
#pragma unroll
                for (int hrow = 0; hrow < 2; hrow++) {
                    int r = hrow ? rb : ra;
                    float* op = hrow ? opb : opa;
                    if (!(hrow ? vb : va)) continue;
                    float4 mm = smeta[r];
                    unsigned u = __float_as_uint(mm.x);
                    const float* b0p = sbias + (u & 0xff) * ODIM;
                    const float* b1p = sbias + ((u >> 8) & 0xff) * ODIM;
                    float gg0 = mm.y, gg1 = mm.z;
                    const int ci = hrow * 2;
#pragma unroll
                    for (int nt = 0; nt < 4; nt++) {
                        int col = nq * 32 + nt * 8 + qk;
                        float2 v;
                        v.x = acc[m][nt][ci] + accB[m][nt][ci]
                            + gg0 * b0p[col] + gg1 * b1p[col];
                        v.y = acc[m][nt][ci + 1] + accB[m][nt][ci + 1]
                            + gg0 * b0p[col + 1] + gg1 * b1p[col + 1];
                        *(float2*)(op + col) = v;
                    }
                }
            } else {
                // load all 8 float2 first (MLP), then add+store
                float2 o[2][4];
#pragma unroll
                for (int nt = 0; nt < 4; nt++) {
                    int col = nq * 32 + nt * 8 + qk;
                    if (va) o[0][nt] = *(float2*)(opa + col);
                    if (vb) o[1][nt] = *(float2*)(opb + col);
                }
#pragma unroll
                for (int nt = 0; nt < 4; nt++) {
                    int col = nq * 32 + nt * 8 + qk;
                    if (va) {
                        float2 v = o[0][nt];
                        v.x += acc[m][nt][0] + accB[m][nt][0];
                        v.y += acc[m][nt][1] + accB[m][nt][1];
                        *(float2*)(opa + col) = v;
                    }
                    if (vb) {
                        float2 v = o[1][nt];
                        v.x += acc[m][nt][2] + accB[m][nt][2];
                        v.y += acc[m][nt][3] + accB[m][nt][3];
                        *(float2*)(opb + col) = v;
                    }
                }
            }
        }
    }
}

// ---------------- launch ----------------
extern "C" void kernel_launch(void* const* d_in, const int* in_sizes, int n_in,
                              void* d_out, int out_size) {
    const float* x  = (const float*)d_in[0];
    const float* wg = (const float*)d_in[1];
    // d_in[2] = w_noise (inactive in eval mode)
    const float* we = (const float*)d_in[3];
    const float* be = (const float*)d_in[4];
    float* out = (float*)d_out;

    cudaFuncSetAttribute(k_gate, cudaFuncAttributeMaxDynamicSharedMemorySize,
                         G_SMEM);
    cudaFuncSetAttribute(k_ffn, cudaFuncAttributeMaxDynamicSharedMemorySize,
                         F_SMEM);

    k_gate<<<NBLK, 128, G_SMEM>>>(x, wg);
    k_scan<<<1, 256>>>();
    k_place<<<NBLK, 128>>>();
    k_ffn<<<GRID3, NTHR_F, F_SMEM>>>(x, we, be, out, 0);
    k_ffn<<<GRID3, NTHR_F, F_SMEM>>>(x, we, be, out, 1);
}